// round 6
// baseline (speedup 1.0000x reference)
#include <cuda_runtime.h>
#include <math.h>

#define B 8
#define N 2048
#define FIN 128
#define FOUT 64
#define ALPHA 0.2f
#define NEG_BIG (-9000000000000000.0f)

#define TI 64
#define TJ 64

// Scratch (allocation-free rule: device globals)
__device__ float g_wh[B * N * FOUT];   // 4 MB
__device__ float g_s1[B * N];
__device__ float g_s2[B * N];
__device__ float g_c[B * N];           // c_i = rowmax + log(rowsum)

// ---------------------------------------------------------------------------
// K1: wh = x @ W ; s1 = wh @ a1 ; s2 = wh @ a2.   One warp per row.
// ---------------------------------------------------------------------------
__global__ __launch_bounds__(256) void k1_proj(const float* __restrict__ x,
                                               const float* __restrict__ W,
                                               const float* __restrict__ w2) {
    __shared__ float xs[8][FIN];
    int warp = threadIdx.x >> 5, lane = threadIdx.x & 31;
    int row = blockIdx.x * 8 + warp;            // [0, B*N)
    const float* xr = x + (size_t)row * FIN;
    xs[warp][lane]      = xr[lane];
    xs[warp][lane + 32] = xr[lane + 32];
    xs[warp][lane + 64] = xr[lane + 64];
    xs[warp][lane + 96] = xr[lane + 96];
    __syncwarp();

    float wh0 = 0.f, wh1 = 0.f;
#pragma unroll 8
    for (int k = 0; k < FIN; ++k) {
        float xv = xs[warp][k];
        wh0 = fmaf(xv, W[k * FOUT + lane],      wh0);
        wh1 = fmaf(xv, W[k * FOUT + lane + 32], wh1);
    }
    g_wh[(size_t)row * FOUT + lane]      = wh0;
    g_wh[(size_t)row * FOUT + lane + 32] = wh1;

    float p1 = wh0 * w2[lane]      + wh1 * w2[lane + 32];
    float p2 = wh0 * w2[64 + lane] + wh1 * w2[96 + lane];
#pragma unroll
    for (int off = 16; off > 0; off >>= 1) {
        p1 += __shfl_xor_sync(0xffffffffu, p1, off);
        p2 += __shfl_xor_sync(0xffffffffu, p2, off);
    }
    if (lane == 0) { g_s1[row] = p1; g_s2[row] = p2; }
}

// ---------------------------------------------------------------------------
// K2: per-row online softmax stats over masked leaky scores.
//     Stores c_i = m_i + log(l_i) so attention = exp(e - c_i) directly.
// ---------------------------------------------------------------------------
__global__ __launch_bounds__(256) void k2_rowstats(const int* __restrict__ adj) {
    int warp = threadIdx.x >> 5, lane = threadIdx.x & 31;
    int row = blockIdx.x * 8 + warp;            // [0, B*N)
    int b = row >> 11;                          // / N
    int i = row & (N - 1);
    const int* arow = adj + ((size_t)b * N + i) * N;
    const float* s2b = g_s2 + b * N;
    float s1v = g_s1[row];

    float m = -3.0e38f, l = 0.f;
    for (int j = lane; j < N; j += 32) {
        int a = arow[j];
        float t = s1v + s2b[j];
        float lk = t > 0.f ? t : ALPHA * t;
        float e = (a > 0) ? lk : NEG_BIG;
        if (e > m) { l = l * __expf(m - e) + 1.f; m = e; }
        else       { l += __expf(e - m); }
    }
    // warp combine (m, l)
#pragma unroll
    for (int off = 16; off > 0; off >>= 1) {
        float mo = __shfl_xor_sync(0xffffffffu, m, off);
        float lo = __shfl_xor_sync(0xffffffffu, l, off);
        float mm = fmaxf(m, mo);
        l = l * __expf(m - mm) + lo * __expf(mo - mm);
        m = mm;
    }
    if (lane == 0) g_c[row] = m + __logf(l);
}

// ---------------------------------------------------------------------------
// K3: out = elu( P @ WH ), P generated on the fly per tile.
//     Block: 64 i-rows, 256 threads; thread = 2 rows x 8 outputs.
//     Accumulate with packed fma.rn.f32x2 (2x fp32 FMA throughput).
// ---------------------------------------------------------------------------
__global__ __launch_bounds__(256) void k3_attn(const int* __restrict__ adj,
                                               float* __restrict__ out) {
    __shared__ float wh_s[TJ][FOUT];        // 16 KB
    __shared__ float p_s[TI][TJ + 1];       // padded: conflict-free row-strided reads
    __shared__ float s2_s[TJ];
    __shared__ float s1_s[TI];
    __shared__ float c_s[TI];

    int t = threadIdx.x;
    int b = blockIdx.y;
    int i0 = blockIdx.x * TI;
    const float* whb = g_wh + (size_t)b * N * FOUT;
    const int* adjb = adj + (size_t)b * N * N;

    if (t < TI) {
        s1_s[t] = g_s1[b * N + i0 + t];
        c_s[t]  = g_c[b * N + i0 + t];
    }

    int cg = t & 7;        // output group: o = cg*8
    int rg = t >> 3;       // 0..31 -> rows rg*2, rg*2+1
    int o = cg * 8;

    unsigned long long acc[2][4];
#pragma unroll
    for (int r = 0; r < 2; ++r)
#pragma unroll
        for (int q = 0; q < 4; ++q) acc[r][q] = 0ull;

    int jq = t & 63;       // j for score phase (coalesced adj)
    int iq = t >> 6;       // 0..3

    for (int jt = 0; jt < N / TJ; ++jt) {
        int j0 = jt * TJ;

        __syncthreads();   // protect wh_s/p_s from previous accumulate phase
        // load WH tile (16 threads x float4 per row, fully coalesced) + s2
#pragma unroll
        for (int q = 0; q < 4; ++q) {
            int lin = t + q * 256;          // 0..1023
            int row = lin >> 4;
            int c4 = (lin & 15) * 4;
            *(float4*)&wh_s[row][c4] =
                *(const float4*)&whb[(size_t)(j0 + row) * FOUT + c4];
        }
        if (t < TJ) s2_s[t] = g_s2[b * N + j0 + t];
        __syncthreads();

        // score phase: p = exp(masked_leaky(s1_i + s2_j) - c_i), one exp per elem
#pragma unroll 4
        for (int q = 0; q < 16; ++q) {
            int i = iq * 16 + q;
            int a = adjb[(size_t)(i0 + i) * N + j0 + jq];
            float tt = s1_s[i] + s2_s[jq];
            float lk = tt > 0.f ? tt : ALPHA * tt;
            float e = (a > 0) ? lk : NEG_BIG;      // keeps all-masked rows exact
            p_s[i][jq] = __expf(e - c_s[i]);
        }
        __syncthreads();

        // accumulate phase: packed f32x2 FMAs, 16 FMA per j per thread
#pragma unroll 4
        for (int j = 0; j < TJ; ++j) {
            ulonglong2 wa = *(const ulonglong2*)&wh_s[j][o];
            ulonglong2 wb = *(const ulonglong2*)&wh_s[j][o + 4];
#pragma unroll
            for (int r = 0; r < 2; ++r) {
                float p = p_s[rg * 2 + r][j];
                unsigned long long pp;
                asm("mov.b64 %0, {%1, %1};" : "=l"(pp) : "r"(__float_as_uint(p)));
                asm("fma.rn.f32x2 %0, %1, %2, %0;" : "+l"(acc[r][0]) : "l"(wa.x), "l"(pp));
                asm("fma.rn.f32x2 %0, %1, %2, %0;" : "+l"(acc[r][1]) : "l"(wa.y), "l"(pp));
                asm("fma.rn.f32x2 %0, %1, %2, %0;" : "+l"(acc[r][2]) : "l"(wb.x), "l"(pp));
                asm("fma.rn.f32x2 %0, %1, %2, %0;" : "+l"(acc[r][3]) : "l"(wb.y), "l"(pp));
            }
        }
    }

    // epilogue: ELU + store
#pragma unroll
    for (int r = 0; r < 2; ++r) {
        int i = i0 + rg * 2 + r;
        float vals[8];
#pragma unroll
        for (int q = 0; q < 4; ++q) {
            vals[q * 2]     = __uint_as_float((unsigned)(acc[r][q] & 0xffffffffu));
            vals[q * 2 + 1] = __uint_as_float((unsigned)(acc[r][q] >> 32));
        }
#pragma unroll
        for (int q = 0; q < 8; ++q) {
            float v = vals[q];
            vals[q] = v > 0.f ? v : (expf(v) - 1.f);
        }
        float4* dst = (float4*)&out[((size_t)b * N + i) * FOUT + o];
        dst[0] = make_float4(vals[0], vals[1], vals[2], vals[3]);
        dst[1] = make_float4(vals[4], vals[5], vals[6], vals[7]);
    }
}

// ---------------------------------------------------------------------------
extern "C" void kernel_launch(void* const* d_in, const int* in_sizes, int n_in,
                              void* d_out, int out_size) {
    const float* x   = (const float*)d_in[0];
    const int*   adj = (const int*)d_in[1];
    const float* W   = (const float*)d_in[2];
    const float* w2  = (const float*)d_in[3];
    float* out = (float*)d_out;

    k1_proj<<<(B * N) / 8, 256>>>(x, W, w2);
    k2_rowstats<<<(B * N) / 8, 256>>>(adj);
    dim3 g3(N / TI, B);
    k3_attn<<<g3, 256>>>(adj, out);
}

// round 7
// speedup vs baseline: 1.0062x; 1.0062x over previous
#include <cuda_runtime.h>
#include <math.h>

#define B 8
#define N 2048
#define FIN 128
#define FOUT 64
#define ALPHA 0.2f
#define NEG_BIG (-9000000000000000.0f)

#define TI 64
#define TJ 64

// Scratch (allocation-free rule: device globals)
__device__ float g_wh[B * N * FOUT];   // 4 MB
__device__ float g_s1[B * N];
__device__ float g_s2[B * N];
__device__ float g_c[B * N];           // c_i = rowmax + log(rowsum)

// ---------------------------------------------------------------------------
// K1: wh = x @ W ; s1 = wh @ a1 ; s2 = wh @ a2.   One warp per row.
// ---------------------------------------------------------------------------
__global__ __launch_bounds__(256) void k1_proj(const float* __restrict__ x,
                                               const float* __restrict__ W,
                                               const float* __restrict__ w2) {
    __shared__ float xs[8][FIN];
    int warp = threadIdx.x >> 5, lane = threadIdx.x & 31;
    int row = blockIdx.x * 8 + warp;            // [0, B*N)
    const float* xr = x + (size_t)row * FIN;
    xs[warp][lane]      = xr[lane];
    xs[warp][lane + 32] = xr[lane + 32];
    xs[warp][lane + 64] = xr[lane + 64];
    xs[warp][lane + 96] = xr[lane + 96];
    __syncwarp();

    float wh0 = 0.f, wh1 = 0.f;
#pragma unroll 8
    for (int k = 0; k < FIN; ++k) {
        float xv = xs[warp][k];
        wh0 = fmaf(xv, W[k * FOUT + lane],      wh0);
        wh1 = fmaf(xv, W[k * FOUT + lane + 32], wh1);
    }
    g_wh[(size_t)row * FOUT + lane]      = wh0;
    g_wh[(size_t)row * FOUT + lane + 32] = wh1;

    float p1 = wh0 * w2[lane]      + wh1 * w2[lane + 32];
    float p2 = wh0 * w2[64 + lane] + wh1 * w2[96 + lane];
#pragma unroll
    for (int off = 16; off > 0; off >>= 1) {
        p1 += __shfl_xor_sync(0xffffffffu, p1, off);
        p2 += __shfl_xor_sync(0xffffffffu, p2, off);
    }
    if (lane == 0) { g_s1[row] = p1; g_s2[row] = p2; }
}

// ---------------------------------------------------------------------------
// K2: per-row online softmax stats over masked leaky scores.
//     Stores c_i = m_i + log(l_i) so attention = exp(e - c_i) directly.
// ---------------------------------------------------------------------------
__global__ __launch_bounds__(256) void k2_rowstats(const int* __restrict__ adj) {
    int warp = threadIdx.x >> 5, lane = threadIdx.x & 31;
    int row = blockIdx.x * 8 + warp;            // [0, B*N)
    int b = row >> 11;                          // / N
    int i = row & (N - 1);
    const int* arow = adj + ((size_t)b * N + i) * N;
    const float* s2b = g_s2 + b * N;
    float s1v = g_s1[row];

    float m = -3.0e38f, l = 0.f;
    for (int j = lane; j < N; j += 32) {
        int a = arow[j];
        float t = s1v + s2b[j];
        float lk = t > 0.f ? t : ALPHA * t;
        float e = (a > 0) ? lk : NEG_BIG;
        if (e > m) { l = l * __expf(m - e) + 1.f; m = e; }
        else       { l += __expf(e - m); }
    }
    // warp combine (m, l)
#pragma unroll
    for (int off = 16; off > 0; off >>= 1) {
        float mo = __shfl_xor_sync(0xffffffffu, m, off);
        float lo = __shfl_xor_sync(0xffffffffu, l, off);
        float mm = fmaxf(m, mo);
        l = l * __expf(m - mm) + lo * __expf(mo - mm);
        m = mm;
    }
    if (lane == 0) g_c[row] = m + __logf(l);
}

// ---------------------------------------------------------------------------
// K3: out = elu( P @ WH ), P generated on the fly per tile.
//     Block: 64 i-rows, 256 threads; thread = 2 rows x 8 outputs.
//     Accumulate with packed fma.rn.f32x2 (2x fp32 FMA throughput).
// ---------------------------------------------------------------------------
__global__ __launch_bounds__(256) void k3_attn(const int* __restrict__ adj,
                                               float* __restrict__ out) {
    __shared__ float wh_s[TJ][FOUT];        // 16 KB
    __shared__ float p_s[TI][TJ + 1];       // padded: conflict-free row-strided reads
    __shared__ float s2_s[TJ];
    __shared__ float s1_s[TI];
    __shared__ float c_s[TI];

    int t = threadIdx.x;
    int b = blockIdx.y;
    int i0 = blockIdx.x * TI;
    const float* whb = g_wh + (size_t)b * N * FOUT;
    const int* adjb = adj + (size_t)b * N * N;

    if (t < TI) {
        s1_s[t] = g_s1[b * N + i0 + t];
        c_s[t]  = g_c[b * N + i0 + t];
    }

    int cg = t & 7;        // output group: o = cg*8
    int rg = t >> 3;       // 0..31 -> rows rg*2, rg*2+1
    int o = cg * 8;

    unsigned long long acc[2][4];
#pragma unroll
    for (int r = 0; r < 2; ++r)
#pragma unroll
        for (int q = 0; q < 4; ++q) acc[r][q] = 0ull;

    int jq = t & 63;       // j for score phase (coalesced adj)
    int iq = t >> 6;       // 0..3

    for (int jt = 0; jt < N / TJ; ++jt) {
        int j0 = jt * TJ;

        __syncthreads();   // protect wh_s/p_s from previous accumulate phase
        // load WH tile (16 threads x float4 per row, fully coalesced) + s2
#pragma unroll
        for (int q = 0; q < 4; ++q) {
            int lin = t + q * 256;          // 0..1023
            int row = lin >> 4;
            int c4 = (lin & 15) * 4;
            *(float4*)&wh_s[row][c4] =
                *(const float4*)&whb[(size_t)(j0 + row) * FOUT + c4];
        }
        if (t < TJ) s2_s[t] = g_s2[b * N + j0 + t];
        __syncthreads();

        // score phase: p = exp(masked_leaky(s1_i + s2_j) - c_i), one exp per elem
#pragma unroll 4
        for (int q = 0; q < 16; ++q) {
            int i = iq * 16 + q;
            int a = adjb[(size_t)(i0 + i) * N + j0 + jq];
            float tt = s1_s[i] + s2_s[jq];
            float lk = tt > 0.f ? tt : ALPHA * tt;
            float e = (a > 0) ? lk : NEG_BIG;      // keeps all-masked rows exact
            p_s[i][jq] = __expf(e - c_s[i]);
        }
        __syncthreads();

        // accumulate phase: packed f32x2 FMAs, 16 FMA per j per thread
#pragma unroll 4
        for (int j = 0; j < TJ; ++j) {
            ulonglong2 wa = *(const ulonglong2*)&wh_s[j][o];
            ulonglong2 wb = *(const ulonglong2*)&wh_s[j][o + 4];
#pragma unroll
            for (int r = 0; r < 2; ++r) {
                float p = p_s[rg * 2 + r][j];
                unsigned long long pp;
                asm("mov.b64 %0, {%1, %1};" : "=l"(pp) : "r"(__float_as_uint(p)));
                asm("fma.rn.f32x2 %0, %1, %2, %0;" : "+l"(acc[r][0]) : "l"(wa.x), "l"(pp));
                asm("fma.rn.f32x2 %0, %1, %2, %0;" : "+l"(acc[r][1]) : "l"(wa.y), "l"(pp));
                asm("fma.rn.f32x2 %0, %1, %2, %0;" : "+l"(acc[r][2]) : "l"(wb.x), "l"(pp));
                asm("fma.rn.f32x2 %0, %1, %2, %0;" : "+l"(acc[r][3]) : "l"(wb.y), "l"(pp));
            }
        }
    }

    // epilogue: ELU + store
#pragma unroll
    for (int r = 0; r < 2; ++r) {
        int i = i0 + rg * 2 + r;
        float vals[8];
#pragma unroll
        for (int q = 0; q < 4; ++q) {
            vals[q * 2]     = __uint_as_float((unsigned)(acc[r][q] & 0xffffffffu));
            vals[q * 2 + 1] = __uint_as_float((unsigned)(acc[r][q] >> 32));
        }
#pragma unroll
        for (int q = 0; q < 8; ++q) {
            float v = vals[q];
            vals[q] = v > 0.f ? v : (expf(v) - 1.f);
        }
        float4* dst = (float4*)&out[((size_t)b * N + i) * FOUT + o];
        dst[0] = make_float4(vals[0], vals[1], vals[2], vals[3]);
        dst[1] = make_float4(vals[4], vals[5], vals[6], vals[7]);
    }
}

// ---------------------------------------------------------------------------
extern "C" void kernel_launch(void* const* d_in, const int* in_sizes, int n_in,
                              void* d_out, int out_size) {
    const float* x   = (const float*)d_in[0];
    const int*   adj = (const int*)d_in[1];
    const float* W   = (const float*)d_in[2];
    const float* w2  = (const float*)d_in[3];
    float* out = (float*)d_out;

    k1_proj<<<(B * N) / 8, 256>>>(x, W, w2);
    k2_rowstats<<<(B * N) / 8, 256>>>(adj);
    dim3 g3(N / TI, B);
    k3_attn<<<g3, 256>>>(adj, out);
}

// round 8
// speedup vs baseline: 1.0077x; 1.0015x over previous
#include <cuda_runtime.h>
#include <math.h>

#define B 8
#define N 2048
#define FIN 128
#define FOUT 64
#define ALPHA 0.2f
#define NEG_BIG (-9000000000000000.0f)

#define TI 64
#define TJ 64

// Scratch (allocation-free rule: device globals)
__device__ float g_wh[B * N * FOUT];   // 4 MB
__device__ float g_s1[B * N];
__device__ float g_s2[B * N];
__device__ float g_c[B * N];           // c_i = rowmax + log(rowsum)

// ---------------------------------------------------------------------------
// K1: wh = x @ W ; s1 = wh @ a1 ; s2 = wh @ a2.   One warp per row.
// ---------------------------------------------------------------------------
__global__ __launch_bounds__(256) void k1_proj(const float* __restrict__ x,
                                               const float* __restrict__ W,
                                               const float* __restrict__ w2) {
    __shared__ float xs[8][FIN];
    int warp = threadIdx.x >> 5, lane = threadIdx.x & 31;
    int row = blockIdx.x * 8 + warp;            // [0, B*N)
    const float* xr = x + (size_t)row * FIN;
    xs[warp][lane]      = xr[lane];
    xs[warp][lane + 32] = xr[lane + 32];
    xs[warp][lane + 64] = xr[lane + 64];
    xs[warp][lane + 96] = xr[lane + 96];
    __syncwarp();

    float wh0 = 0.f, wh1 = 0.f;
#pragma unroll 8
    for (int k = 0; k < FIN; ++k) {
        float xv = xs[warp][k];
        wh0 = fmaf(xv, W[k * FOUT + lane],      wh0);
        wh1 = fmaf(xv, W[k * FOUT + lane + 32], wh1);
    }
    g_wh[(size_t)row * FOUT + lane]      = wh0;
    g_wh[(size_t)row * FOUT + lane + 32] = wh1;

    float p1 = wh0 * w2[lane]      + wh1 * w2[lane + 32];
    float p2 = wh0 * w2[64 + lane] + wh1 * w2[96 + lane];
#pragma unroll
    for (int off = 16; off > 0; off >>= 1) {
        p1 += __shfl_xor_sync(0xffffffffu, p1, off);
        p2 += __shfl_xor_sync(0xffffffffu, p2, off);
    }
    if (lane == 0) { g_s1[row] = p1; g_s2[row] = p2; }
}

// ---------------------------------------------------------------------------
// K2: per-row online softmax stats over masked leaky scores.
//     Stores c_i = m_i + log(l_i) so attention = exp(e - c_i) directly.
// ---------------------------------------------------------------------------
__global__ __launch_bounds__(256) void k2_rowstats(const int* __restrict__ adj) {
    int warp = threadIdx.x >> 5, lane = threadIdx.x & 31;
    int row = blockIdx.x * 8 + warp;            // [0, B*N)
    int b = row >> 11;                          // / N
    int i = row & (N - 1);
    const int* arow = adj + ((size_t)b * N + i) * N;
    const float* s2b = g_s2 + b * N;
    float s1v = g_s1[row];

    float m = -3.0e38f, l = 0.f;
    for (int j = lane; j < N; j += 32) {
        int a = arow[j];
        float t = s1v + s2b[j];
        float lk = t > 0.f ? t : ALPHA * t;
        float e = (a > 0) ? lk : NEG_BIG;
        if (e > m) { l = l * __expf(m - e) + 1.f; m = e; }
        else       { l += __expf(e - m); }
    }
    // warp combine (m, l)
#pragma unroll
    for (int off = 16; off > 0; off >>= 1) {
        float mo = __shfl_xor_sync(0xffffffffu, m, off);
        float lo = __shfl_xor_sync(0xffffffffu, l, off);
        float mm = fmaxf(m, mo);
        l = l * __expf(m - mm) + lo * __expf(mo - mm);
        m = mm;
    }
    if (lane == 0) g_c[row] = m + __logf(l);
}

// ---------------------------------------------------------------------------
// K3: out = elu( P @ WH ), P generated on the fly per tile.
//     Block: 64 i-rows, 256 threads; thread = 2 rows x 8 outputs.
//     Accumulate with packed fma.rn.f32x2 (2x fp32 FMA throughput).
// ---------------------------------------------------------------------------
__global__ __launch_bounds__(256) void k3_attn(const int* __restrict__ adj,
                                               float* __restrict__ out) {
    __shared__ float wh_s[TJ][FOUT];        // 16 KB
    __shared__ float p_s[TI][TJ + 1];       // padded: conflict-free row-strided reads
    __shared__ float s2_s[TJ];
    __shared__ float s1_s[TI];
    __shared__ float c_s[TI];

    int t = threadIdx.x;
    int b = blockIdx.y;
    int i0 = blockIdx.x * TI;
    const float* whb = g_wh + (size_t)b * N * FOUT;
    const int* adjb = adj + (size_t)b * N * N;

    if (t < TI) {
        s1_s[t] = g_s1[b * N + i0 + t];
        c_s[t]  = g_c[b * N + i0 + t];
    }

    int cg = t & 7;        // output group: o = cg*8
    int rg = t >> 3;       // 0..31 -> rows rg*2, rg*2+1
    int o = cg * 8;

    unsigned long long acc[2][4];
#pragma unroll
    for (int r = 0; r < 2; ++r)
#pragma unroll
        for (int q = 0; q < 4; ++q) acc[r][q] = 0ull;

    int jq = t & 63;       // j for score phase (coalesced adj)
    int iq = t >> 6;       // 0..3

    for (int jt = 0; jt < N / TJ; ++jt) {
        int j0 = jt * TJ;

        __syncthreads();   // protect wh_s/p_s from previous accumulate phase
        // load WH tile (16 threads x float4 per row, fully coalesced) + s2
#pragma unroll
        for (int q = 0; q < 4; ++q) {
            int lin = t + q * 256;          // 0..1023
            int row = lin >> 4;
            int c4 = (lin & 15) * 4;
            *(float4*)&wh_s[row][c4] =
                *(const float4*)&whb[(size_t)(j0 + row) * FOUT + c4];
        }
        if (t < TJ) s2_s[t] = g_s2[b * N + j0 + t];
        __syncthreads();

        // score phase: p = exp(masked_leaky(s1_i + s2_j) - c_i), one exp per elem
#pragma unroll 4
        for (int q = 0; q < 16; ++q) {
            int i = iq * 16 + q;
            int a = adjb[(size_t)(i0 + i) * N + j0 + jq];
            float tt = s1_s[i] + s2_s[jq];
            float lk = tt > 0.f ? tt : ALPHA * tt;
            float e = (a > 0) ? lk : NEG_BIG;      // keeps all-masked rows exact
            p_s[i][jq] = __expf(e - c_s[i]);
        }
        __syncthreads();

        // accumulate phase: packed f32x2 FMAs, 16 FMA per j per thread
#pragma unroll 4
        for (int j = 0; j < TJ; ++j) {
            ulonglong2 wa = *(const ulonglong2*)&wh_s[j][o];
            ulonglong2 wb = *(const ulonglong2*)&wh_s[j][o + 4];
#pragma unroll
            for (int r = 0; r < 2; ++r) {
                float p = p_s[rg * 2 + r][j];
                unsigned long long pp;
                asm("mov.b64 %0, {%1, %1};" : "=l"(pp) : "r"(__float_as_uint(p)));
                asm("fma.rn.f32x2 %0, %1, %2, %0;" : "+l"(acc[r][0]) : "l"(wa.x), "l"(pp));
                asm("fma.rn.f32x2 %0, %1, %2, %0;" : "+l"(acc[r][1]) : "l"(wa.y), "l"(pp));
                asm("fma.rn.f32x2 %0, %1, %2, %0;" : "+l"(acc[r][2]) : "l"(wb.x), "l"(pp));
                asm("fma.rn.f32x2 %0, %1, %2, %0;" : "+l"(acc[r][3]) : "l"(wb.y), "l"(pp));
            }
        }
    }

    // epilogue: ELU + store
#pragma unroll
    for (int r = 0; r < 2; ++r) {
        int i = i0 + rg * 2 + r;
        float vals[8];
#pragma unroll
        for (int q = 0; q < 4; ++q) {
            vals[q * 2]     = __uint_as_float((unsigned)(acc[r][q] & 0xffffffffu));
            vals[q * 2 + 1] = __uint_as_float((unsigned)(acc[r][q] >> 32));
        }
#pragma unroll
        for (int q = 0; q < 8; ++q) {
            float v = vals[q];
            vals[q] = v > 0.f ? v : (expf(v) - 1.f);
        }
        float4* dst = (float4*)&out[((size_t)b * N + i) * FOUT + o];
        dst[0] = make_float4(vals[0], vals[1], vals[2], vals[3]);
        dst[1] = make_float4(vals[4], vals[5], vals[6], vals[7]);
    }
}

// ---------------------------------------------------------------------------
extern "C" void kernel_launch(void* const* d_in, const int* in_sizes, int n_in,
                              void* d_out, int out_size) {
    const float* x   = (const float*)d_in[0];
    const int*   adj = (const int*)d_in[1];
    const float* W   = (const float*)d_in[2];
    const float* w2  = (const float*)d_in[3];
    float* out = (float*)d_out;

    k1_proj<<<(B * N) / 8, 256>>>(x, W, w2);
    k2_rowstats<<<(B * N) / 8, 256>>>(adj);
    dim3 g3(N / TI, B);
    k3_attn<<<g3, 256>>>(adj, out);
}